// round 1
// baseline (speedup 1.0000x reference)
#include <cuda_runtime.h>
#include <cstdint>

#define N_PTS    4096
#define N_QUERY  35328     // 64*552
#define NSAMPLE  32
#define FEAT_D   32
#define FEAT_H   64
#define OUT_BASE 384       // 64*6 src_keypts floats precede grouped output
#define ROW      35        // 3+FEAT_D
#define QROW     1120      // NSAMPLE*ROW

// -------- scratch (static device globals: allocation-free) --------
__device__ float4 g_xyzp[N_PTS];             // tgt xyz + |p|^2
__device__ float  g_feat[N_PTS * FEAT_D];    // tgt feature rows [n][32]
__device__ float  g_scores[N_PTS];           // src softplus scores

// monotone float -> uint mapping (total order incl. negatives)
__device__ __forceinline__ unsigned int fmap(float f) {
    unsigned int u = __float_as_uint(f);
    return (u & 0x80000000u) ? ~u : (u | 0x80000000u);
}
__device__ __forceinline__ unsigned long long umin64(unsigned long long a, unsigned long long b) {
    return a < b ? a : b;
}
__device__ __forceinline__ unsigned long long umax64(unsigned long long a, unsigned long long b) {
    return a > b ? a : b;
}

// ---------------------------------------------------------------
// Kernel 1: feature MLP. mode==0: tgt (write g_xyzp + g_feat)
//           mode==1: src (write g_scores)
// fp32 op order mirrors the XLA reference (fma-chain contractions).
// ---------------------------------------------------------------
__global__ void __launch_bounds__(128) feat_kernel(
    const float* __restrict__ pts,
    const float* __restrict__ W1, const float* __restrict__ b1,
    const float* __restrict__ W2, const float* __restrict__ b2,
    const float* __restrict__ Wq, const float* __restrict__ bq,
    int mode)
{
    __shared__ float sW1[FEAT_H * 6], sb1[FEAT_H];
    __shared__ float sW2[FEAT_D * FEAT_H], sb2[FEAT_D];
    __shared__ float sWq[FEAT_D], sbq;

    int tid = threadIdx.x;
    for (int i = tid; i < FEAT_H * 6;      i += 128) sW1[i] = W1[i];
    for (int i = tid; i < FEAT_H;          i += 128) sb1[i] = b1[i];
    for (int i = tid; i < FEAT_D * FEAT_H; i += 128) sW2[i] = W2[i];
    for (int i = tid; i < FEAT_D;          i += 128) sb2[i] = b2[i];
    for (int i = tid; i < FEAT_D;          i += 128) sWq[i] = Wq[i];
    if (tid == 0) sbq = bq[0];
    __syncthreads();

    int n = blockIdx.x * 128 + tid;
    if (n >= N_PTS) return;

    float x[6];
#pragma unroll
    for (int c = 0; c < 6; c++) x[c] = pts[c * N_PTS + n];

    float h[FEAT_H];
#pragma unroll
    for (int o = 0; o < FEAT_H; o++) {
        float acc = __fmul_rn(sW1[o * 6], x[0]);
#pragma unroll
        for (int c = 1; c < 6; c++) acc = __fmaf_rn(sW1[o * 6 + c], x[c], acc);
        h[o] = fmaxf(__fadd_rn(acc, sb1[o]), 0.0f);
    }

    float z = 0.0f;
#pragma unroll
    for (int o = 0; o < FEAT_D; o++) {
        float acc = __fmul_rn(sW2[o * FEAT_H], h[0]);
#pragma unroll
        for (int k = 1; k < FEAT_H; k++) acc = __fmaf_rn(sW2[o * FEAT_H + k], h[k], acc);
        float f = fmaxf(__fadd_rn(acc, sb2[o]), 0.0f);
        if (mode == 0) {
            g_feat[n * FEAT_D + o] = f;
        } else {
            z = (o == 0) ? __fmul_rn(sWq[0], f) : __fmaf_rn(sWq[o], f, z);
        }
    }

    if (mode == 0) {
        float pp = __fadd_rn(__fadd_rn(__fmul_rn(x[0], x[0]), __fmul_rn(x[1], x[1])),
                             __fmul_rn(x[2], x[2]));
        g_xyzp[n] = make_float4(x[0], x[1], x[2], pp);
    } else {
        z = __fadd_rn(z, sbq);
        // jax.nn.softplus = logaddexp(z, 0) = max(z,0) + log1p(exp(-|z|))
        float sp = __fadd_rn(fmaxf(z, 0.0f), log1pf(expf(-fabsf(z))));
        g_scores[n] = sp;
    }
}

// ---------------------------------------------------------------
// Kernel 2: src top-64 (descending score, tie -> lower index),
// then gather src_keypts [64,6] into out[0..383].
// ---------------------------------------------------------------
__global__ void topk_src_kernel(const float* __restrict__ src_pts,
                                float* __restrict__ out)
{
    __shared__ unsigned long long skey[N_PTS];   // 32 KB
    __shared__ unsigned long long sred[256];
    __shared__ int ssel[64];

    int tid = threadIdx.x;
    for (int i = tid; i < N_PTS; i += 256) {
        skey[i] = ((unsigned long long)fmap(g_scores[i]) << 32) |
                  (unsigned long long)(0xFFFFFFFFu - (unsigned)i);
    }
    __syncthreads();

    for (int k = 0; k < 64; k++) {
        unsigned long long best = 0ull;
        for (int i = tid; i < N_PTS; i += 256) best = umax64(best, skey[i]);
        sred[tid] = best;
        __syncthreads();
        for (int s = 128; s > 0; s >>= 1) {
            if (tid < s) sred[tid] = umax64(sred[tid], sred[tid + s]);
            __syncthreads();
        }
        unsigned long long b = sred[0];
        int w = (int)(0xFFFFFFFFu - (unsigned)(b & 0xFFFFFFFFull));
        if (tid == 0) { ssel[k] = w; skey[w] = 0ull; }
        __syncthreads();
    }

    for (int e = tid; e < 384; e += 256) {
        int kk = e / 6, c = e - kk * 6;
        out[e] = src_pts[c * N_PTS + ssel[kk]];
    }
}

// ---------------------------------------------------------------
// Kernel 3: ball query nearest-32 + gather. One block per query.
// Exact top_k semantics: ascending (dist, idx) lexicographic among
// dist <= 4.0; invalid slots padded with slot-0 index (0 if none valid).
// ---------------------------------------------------------------
__global__ void __launch_bounds__(128) ball_kernel(
    const float* __restrict__ cand,
    float* __restrict__ out)
{
    __shared__ float sdist[N_PTS];               // 16 KB
    __shared__ unsigned long long schunk[128];   // per-32-point chunk minima
    __shared__ int ssel[NSAMPLE];

    const unsigned long long INVK = ~0ull;
    int tid = threadIdx.x;
    int qid = blockIdx.x;

    float q0 = __ldg(&cand[qid * 3 + 0]);
    float q1 = __ldg(&cand[qid * 3 + 1]);
    float q2 = __ldg(&cand[qid * 3 + 2]);
    float qq = __fadd_rn(__fadd_rn(__fmul_rn(q0, q0), __fmul_rn(q1, q1)),
                         __fmul_rn(q2, q2));

    // Pass 1: distances (reference formula: qq - 2*dot + pp)
#pragma unroll 4
    for (int j = 0; j < 32; j++) {
        int p = tid + 128 * j;
        float4 P = g_xyzp[p];
        float E = __fmaf_rn(P.z, q2, __fmaf_rn(P.y, q1, __fmul_rn(P.x, q0)));
        float d = __fadd_rn(__fsub_rn(qq, __fmul_rn(2.0f, E)), P.w);
        sdist[p] = d;
    }
    __syncthreads();

    // Per-chunk minima (chunk c = points [32c, 32c+32)), staggered banks
    {
        int c = tid;
        unsigned long long best = INVK;
        for (int j = 0; j < 32; j++) {
            int i = (c << 5) + ((j + c) & 31);
            float d = sdist[i];
            if (d <= 4.0f) {
                unsigned long long key =
                    ((unsigned long long)fmap(d) << 32) | (unsigned long long)(unsigned)i;
                best = umin64(best, key);
            }
        }
        schunk[c] = best;
    }
    __syncthreads();

    // Tournament delete-min by warp 0: 32 extractions
    if (tid < 32) {
        int sel0 = 0;
        for (int k = 0; k < NSAMPLE; k++) {
            unsigned long long b = INVK;
#pragma unroll
            for (int j = 0; j < 4; j++) b = umin64(b, schunk[tid + 32 * j]);
#pragma unroll
            for (int off = 16; off; off >>= 1)
                b = umin64(b, __shfl_xor_sync(0xffffffffu, b, off));

            int w;
            if (b != INVK) {
                w = (int)(unsigned)(b & 0xFFFFFFFFull);
                int cidx = w >> 5;
                if (tid == 0) sdist[w] = __int_as_float(0x7f800000); // +inf: excluded
                __syncwarp();
                int i2 = (cidx << 5) + tid;
                float d2 = sdist[i2];
                unsigned long long key2 = (d2 <= 4.0f)
                    ? (((unsigned long long)fmap(d2) << 32) | (unsigned long long)(unsigned)i2)
                    : INVK;
#pragma unroll
                for (int off = 16; off; off >>= 1)
                    key2 = umin64(key2, __shfl_xor_sync(0xffffffffu, key2, off));
                if (tid == 0) schunk[cidx] = key2;
                __syncwarp();
            } else {
                w = (k == 0) ? 0 : sel0;   // padding with slot-0 index
            }
            if (k == 0) sel0 = w;
            if (tid == 0) ssel[k] = w;
            __syncwarp();
        }
    }
    __syncthreads();

    // Output: [NSAMPLE][3+FEAT_D] per query, contiguous
    long long base = (long long)OUT_BASE + (long long)qid * QROW;
    for (int e = tid; e < QROW; e += 128) {
        int s = e / ROW;
        int c = e - s * ROW;
        int idx = ssel[s];
        float val;
        if (c < 3) {
            const float* Pf = (const float*)&g_xyzp[idx];
            float qc = (c == 0) ? q0 : ((c == 1) ? q1 : q2);
            val = __fsub_rn(Pf[c], qc);
        } else {
            val = g_feat[idx * FEAT_D + (c - 3)];
        }
        out[base + e] = val;
    }
}

// ---------------------------------------------------------------
extern "C" void kernel_launch(void* const* d_in, const int* in_sizes, int n_in,
                              void* d_out, int out_size)
{
    const float* src_pts = (const float*)d_in[0];
    const float* tgt_pts = (const float*)d_in[1];
    const float* cand    = (const float*)d_in[2];
    const float* W1      = (const float*)d_in[3];
    const float* b1      = (const float*)d_in[4];
    const float* W2      = (const float*)d_in[5];
    const float* b2      = (const float*)d_in[6];
    const float* Wq      = (const float*)d_in[7];
    const float* bq      = (const float*)d_in[8];
    float* out = (float*)d_out;

    feat_kernel<<<N_PTS / 128, 128>>>(tgt_pts, W1, b1, W2, b2, Wq, bq, 0);
    feat_kernel<<<N_PTS / 128, 128>>>(src_pts, W1, b1, W2, b2, Wq, bq, 1);
    topk_src_kernel<<<1, 256>>>(src_pts, out);
    ball_kernel<<<N_QUERY, 128>>>(cand, out);
}

// round 4
// speedup vs baseline: 1.2788x; 1.2788x over previous
#include <cuda_runtime.h>
#include <cstdint>

#define N_PTS    4096
#define N_QUERY  35328     // 64*552
#define NSAMPLE  32
#define FEAT_D   32
#define FEAT_H   64
#define OUT_BASE 384       // 64*6 src_keypts floats precede grouped output
#define ROW      35        // 3+FEAT_D
#define QROW     1120      // NSAMPLE*ROW
#define NBUCKET  2048
#define CAND_CAP 64

// -------- scratch (static device globals: allocation-free) --------
__device__ float4 g_xyzp[N_PTS];             // tgt xyz + |p|^2
__device__ float  g_feat[N_PTS * FEAT_D];    // tgt feature rows [n][32]
__device__ float  g_scores[N_PTS];           // src softplus scores

// monotone float -> uint mapping (total order incl. negatives)
__device__ __forceinline__ unsigned int fmap(float f) {
    unsigned int u = __float_as_uint(f);
    return (u & 0x80000000u) ? ~u : (u | 0x80000000u);
}
__device__ __forceinline__ unsigned long long umin64(unsigned long long a, unsigned long long b) {
    return a < b ? a : b;
}
__device__ __forceinline__ unsigned long long umax64(unsigned long long a, unsigned long long b) {
    return a > b ? a : b;
}
__device__ __forceinline__ unsigned long long shfl_xor64(unsigned long long v, int m) {
    return __shfl_xor_sync(0xffffffffu, v, m);
}

// ---------------------------------------------------------------
// Kernel 1: feature MLP (fused src+tgt via blockIdx.y).
//   y==0: tgt (write g_xyzp + g_feat);  y==1: src (write g_scores)
// fp32 op order mirrors the XLA reference (fma-chain contractions).
// ---------------------------------------------------------------
__global__ void __launch_bounds__(128) feat_kernel(
    const float* __restrict__ tgt_pts,
    const float* __restrict__ src_pts,
    const float* __restrict__ W1, const float* __restrict__ b1,
    const float* __restrict__ W2, const float* __restrict__ b2,
    const float* __restrict__ Wq, const float* __restrict__ bq)
{
    __shared__ float sW1[FEAT_H * 6], sb1[FEAT_H];
    __shared__ float sW2[FEAT_D * FEAT_H], sb2[FEAT_D];
    __shared__ float sWq[FEAT_D], sbq;

    int tid  = threadIdx.x;
    int mode = blockIdx.y;           // 0 = tgt, 1 = src
    const float* pts = mode ? src_pts : tgt_pts;

    for (int i = tid; i < FEAT_H * 6;      i += 128) sW1[i] = W1[i];
    for (int i = tid; i < FEAT_H;          i += 128) sb1[i] = b1[i];
    for (int i = tid; i < FEAT_D * FEAT_H; i += 128) sW2[i] = W2[i];
    for (int i = tid; i < FEAT_D;          i += 128) sb2[i] = b2[i];
    for (int i = tid; i < FEAT_D;          i += 128) sWq[i] = Wq[i];
    if (tid == 0) sbq = bq[0];
    __syncthreads();

    int n = blockIdx.x * 128 + tid;

    float x[6];
#pragma unroll
    for (int c = 0; c < 6; c++) x[c] = pts[c * N_PTS + n];

    float h[FEAT_H];
#pragma unroll
    for (int o = 0; o < FEAT_H; o++) {
        float acc = __fmul_rn(sW1[o * 6], x[0]);
#pragma unroll
        for (int c = 1; c < 6; c++) acc = __fmaf_rn(sW1[o * 6 + c], x[c], acc);
        h[o] = fmaxf(__fadd_rn(acc, sb1[o]), 0.0f);
    }

    float z = 0.0f;
#pragma unroll
    for (int o = 0; o < FEAT_D; o++) {
        float acc = __fmul_rn(sW2[o * FEAT_H], h[0]);
#pragma unroll
        for (int k = 1; k < FEAT_H; k++) acc = __fmaf_rn(sW2[o * FEAT_H + k], h[k], acc);
        float f = fmaxf(__fadd_rn(acc, sb2[o]), 0.0f);
        if (mode == 0) {
            g_feat[n * FEAT_D + o] = f;
        } else {
            z = (o == 0) ? __fmul_rn(sWq[0], f) : __fmaf_rn(sWq[o], f, z);
        }
    }

    if (mode == 0) {
        float pp = __fadd_rn(__fadd_rn(__fmul_rn(x[0], x[0]), __fmul_rn(x[1], x[1])),
                             __fmul_rn(x[2], x[2]));
        g_xyzp[n] = make_float4(x[0], x[1], x[2], pp);
    } else {
        z = __fadd_rn(z, sbq);
        // jax.nn.softplus = max(z,0) + log1p(exp(-|z|))
        float sp = __fadd_rn(fmaxf(z, 0.0f), log1pf(expf(-fabsf(z))));
        g_scores[n] = sp;
    }
}

// ---------------------------------------------------------------
// Kernel 2: src top-64 (descending score, tie -> lower index) via
// chunk-max cache + warp tournament; then gather src_keypts [64,6].
// ---------------------------------------------------------------
__global__ void __launch_bounds__(128) topk_src_kernel(
    const float* __restrict__ src_pts, float* __restrict__ out)
{
    __shared__ float ss[N_PTS];                  // 16 KB
    __shared__ unsigned long long schunk[128];
    __shared__ int ssel[64];

    int tid = threadIdx.x;
    for (int i = tid; i < N_PTS; i += 128) ss[i] = g_scores[i];
    __syncthreads();

    // per-32-element chunk maxima (staggered to dodge bank conflicts)
    {
        int c = tid;
        unsigned long long best = 0ull;
        for (int j = 0; j < 32; j++) {
            int i = (c << 5) + ((j + c) & 31);
            unsigned long long key = ((unsigned long long)fmap(ss[i]) << 32) |
                                     (unsigned long long)(0xFFFFFFFFu - (unsigned)i);
            best = umax64(best, key);
        }
        schunk[c] = best;
    }
    __syncthreads();

    if (tid < 32) {
        for (int k = 0; k < 64; k++) {
            unsigned long long b = 0ull;
#pragma unroll
            for (int j = 0; j < 4; j++) b = umax64(b, schunk[tid + 32 * j]);
#pragma unroll
            for (int off = 16; off; off >>= 1)
                b = umax64(b, shfl_xor64(b, off));

            int w = (int)(0xFFFFFFFFu - (unsigned)(b & 0xFFFFFFFFull));
            int cidx = w >> 5;
            if (tid == 0) ss[w] = __int_as_float(0xFF800000); // -inf: removed
            __syncwarp();
            int i2 = (cidx << 5) + tid;
            unsigned long long key2 = ((unsigned long long)fmap(ss[i2]) << 32) |
                                      (unsigned long long)(0xFFFFFFFFu - (unsigned)i2);
#pragma unroll
            for (int off = 16; off; off >>= 1)
                key2 = umax64(key2, shfl_xor64(key2, off));
            if (tid == 0) { schunk[cidx] = key2; ssel[k] = w; }
            __syncwarp();
        }
    }
    __syncthreads();

    for (int e = tid; e < 384; e += 128) {
        int kk = e / 6, c = e - kk * 6;
        out[e] = src_pts[c * N_PTS + ssel[kk]];
    }
}

// ---------------------------------------------------------------
// Kernel 3: ball query nearest-32 + gather. One block per query.
// Histogram prefilter (2048 buckets on d in [0,4]) -> small exact
// candidate set -> 64-wide bitonic sort in warp 0 on (fmap(d),idx).
// Exact top_k semantics preserved; exact fallback on overflow.
// ---------------------------------------------------------------
__global__ void __launch_bounds__(128) ball_kernel(
    const float* __restrict__ cand,
    float* __restrict__ out)
{
    __shared__ float sdist[N_PTS];               // 16 KB
    __shared__ unsigned int hist[NBUCKET];       // 8 KB
    __shared__ int spart[128];
    __shared__ unsigned long long scand[CAND_CAP];
    __shared__ unsigned long long sred[128];
    __shared__ int ssel[NSAMPLE];
    __shared__ int scut, scnt;

    const unsigned long long INVK = ~0ull;
    int tid = threadIdx.x;
    int qid = blockIdx.x;

    for (int i = tid; i < NBUCKET; i += 128) hist[i] = 0;
    if (tid == 0) { scut = NBUCKET - 1; scnt = 0; }

    float q0 = __ldg(&cand[qid * 3 + 0]);
    float q1 = __ldg(&cand[qid * 3 + 1]);
    float q2 = __ldg(&cand[qid * 3 + 2]);
    float qq = __fadd_rn(__fadd_rn(__fmul_rn(q0, q0), __fmul_rn(q1, q1)),
                         __fmul_rn(q2, q2));
    __syncthreads();

    // Pass 1: distances (reference formula: qq - 2*dot + pp) + histogram
#pragma unroll 4
    for (int j = 0; j < 32; j++) {
        int p = j * 128 + tid;
        float4 P = g_xyzp[p];
        float E = __fmaf_rn(P.z, q2, __fmaf_rn(P.y, q1, __fmul_rn(P.x, q0)));
        float d = __fadd_rn(__fsub_rn(qq, __fmul_rn(2.0f, E)), P.w);
        sdist[p] = d;
        if (d <= 4.0f) {
            int b = (int)(d * 512.0f);
            b = b < 0 ? 0 : (b > NBUCKET - 1 ? NBUCKET - 1 : b);
            atomicAdd(&hist[b], 1u);
        }
    }
    __syncthreads();

    // Scan 128 x 16-bucket partials to locate the cut bucket
    int base = tid * 16;
    int psum = 0;
#pragma unroll
    for (int t = 0; t < 16; t++) psum += hist[base + t];
    spart[tid] = psum;
    __syncthreads();
    for (int off = 1; off < 128; off <<= 1) {
        int v = (tid >= off) ? spart[tid - off] : 0;
        __syncthreads();
        spart[tid] += v;
        __syncthreads();
    }
    int total = spart[127];
    int incl  = spart[tid];
    int excl  = incl - psum;
    if (total >= NSAMPLE && excl < NSAMPLE && incl >= NSAMPLE) {
        int run = excl;
#pragma unroll
        for (int t = 0; t < 16; t++) {
            run += hist[base + t];
            if (run >= NSAMPLE) { scut = base + t; break; }
        }
    }
    __syncthreads();
    int cut = scut;

    // Pass 2: collect candidates with bucket <= cut
    for (int j = 0; j < 32; j++) {
        int p = j * 128 + tid;
        float d = sdist[p];
        if (d <= 4.0f) {
            int b = (int)(d * 512.0f);
            b = b < 0 ? 0 : (b > NBUCKET - 1 ? NBUCKET - 1 : b);
            if (b <= cut) {
                int pos = atomicAdd(&scnt, 1);
                if (pos < CAND_CAP)
                    scand[pos] = ((unsigned long long)fmap(d) << 32) |
                                 (unsigned long long)(unsigned)p;
            }
        }
    }
    __syncthreads();
    int cnt = scnt;

    if (cnt <= CAND_CAP) {
        // warp 0: 64-element bitonic sort (2 keys per lane), ascending
        if (tid < 32) {
            unsigned long long a = (tid      < cnt) ? scand[tid]      : INVK;
            unsigned long long b = (tid + 32 < cnt) ? scand[tid + 32] : INVK;
            for (int k = 2; k <= 64; k <<= 1) {
                for (int j = k >> 1; j > 0; j >>= 1) {
                    if (j == 32) {
                        // cross-register exchange (only at k==64 -> ascending)
                        unsigned long long lo = umin64(a, b), hi = umax64(a, b);
                        a = lo; b = hi;
                    } else {
                        {
                            unsigned long long o = shfl_xor64(a, j);
                            bool asc = ((tid & k) == 0);
                            bool keepmin = (((tid & j) == 0) == asc);
                            a = keepmin ? umin64(a, o) : umax64(a, o);
                        }
                        {
                            unsigned long long o = shfl_xor64(b, j);
                            bool asc = (((tid + 32) & k) == 0);
                            bool keepmin = (((tid & j) == 0) == asc);
                            b = keepmin ? umin64(b, o) : umax64(b, o);
                        }
                    }
                }
            }
            // lane t holds the t-th smallest in `a`
            unsigned long long a0 = __shfl_sync(0xffffffffu, a, 0);
            int myidx = (int)(unsigned)(a & 0xFFFFFFFFull);
            int idx0  = (int)(unsigned)(a0 & 0xFFFFFFFFull);
            bool av = (a != INVK), v0 = (a0 != INVK);
            ssel[tid] = av ? myidx : (v0 ? idx0 : 0);
        }
    } else {
        // exact fallback (degenerate tie explosion): 32 block-wide argmins
        for (int k = 0; k < NSAMPLE; k++) {
            unsigned long long best = INVK;
            for (int j = 0; j < 32; j++) {
                int p = j * 128 + tid;
                float d = sdist[p];
                if (d <= 4.0f)
                    best = umin64(best, ((unsigned long long)fmap(d) << 32) |
                                        (unsigned long long)(unsigned)p);
            }
            sred[tid] = best;
            __syncthreads();
            for (int st = 64; st; st >>= 1) {
                if (tid < st) sred[tid] = umin64(sred[tid], sred[tid + st]);
                __syncthreads();
            }
            unsigned long long bb = sred[0];
            int w = (bb != INVK) ? (int)(unsigned)(bb & 0xFFFFFFFFull)
                                 : (k ? ssel[0] : 0);
            if (tid == 0) {
                ssel[k] = w;
                if (bb != INVK) sdist[w] = __int_as_float(0x7F800000);
            }
            __syncthreads();
        }
    }
    __syncthreads();

    // Output: [NSAMPLE][3+FEAT_D] per query, vectorized float4 stores
    float4* ob = (float4*)(out + OUT_BASE + (long long)qid * QROW);
    for (int v = tid; v < QROW / 4; v += 128) {
        int e = v * 4;
        int s = e / ROW;
        int c = e - s * ROW;
        float r[4];
#pragma unroll
        for (int t = 0; t < 4; t++) {
            int idx = ssel[s];
            float val;
            if (c < 3) {
                const float* Pf = (const float*)&g_xyzp[idx];
                float qc = (c == 0) ? q0 : ((c == 1) ? q1 : q2);
                val = __fsub_rn(Pf[c], qc);
            } else {
                val = g_feat[idx * FEAT_D + (c - 3)];
            }
            r[t] = val;
            if (++c == ROW) { c = 0; ++s; }
        }
        ob[v] = make_float4(r[0], r[1], r[2], r[3]);
    }
}

// ---------------------------------------------------------------
extern "C" void kernel_launch(void* const* d_in, const int* in_sizes, int n_in,
                              void* d_out, int out_size)
{
    const float* src_pts = (const float*)d_in[0];
    const float* tgt_pts = (const float*)d_in[1];
    const float* cand    = (const float*)d_in[2];
    const float* W1      = (const float*)d_in[3];
    const float* b1      = (const float*)d_in[4];
    const float* W2      = (const float*)d_in[5];
    const float* b2      = (const float*)d_in[6];
    const float* Wq      = (const float*)d_in[7];
    const float* bq      = (const float*)d_in[8];
    float* out = (float*)d_out;

    feat_kernel<<<dim3(N_PTS / 128, 2), 128>>>(tgt_pts, src_pts, W1, b1, W2, b2, Wq, bq);
    topk_src_kernel<<<1, 128>>>(src_pts, out);
    ball_kernel<<<N_QUERY, 128>>>(cand, out);
}